// round 4
// baseline (speedup 1.0000x reference)
#include <cuda_runtime.h>
#include <cstdint>

// ============================================================================
// TargetMLPReadout on sm_103a — mma.sync tf32 fused kernel (round 3 resubmit;
// rounds 1-2 never ran: GPU broker at capacity)
//   out[b] = sum_{n=1..63} relu(relu([t_b;e_bn]@W1 + b1)@W2 + b2)
// Restructured:
//   a_b = t_b@W1_top + b1           (per-batch, full fp32 SIMT)
//   h1  = relu(e@W1_bot + a_b)      (tf32 mma.sync, 258048x128x128)
//   h2  = relu(h1@W2 + b2)          (tf32 mma.sync, 258048x128x128)
//   out[b] = sum over 63 rows of h2
// ============================================================================

#define DIMV     128
#define NODES    64
#define NBATCH   4096
#define BPC      8            // batches per CTA
#define NTHREADS 256

// shared memory layout (in floats)
#define XB_STRIDE 132
#define WB_STRIDE 136
#define XB_OFF  0
#define W1B_OFF (128 * XB_STRIDE)                 // 16896
#define W2B_OFF (W1B_OFF + 128 * WB_STRIDE)       // 34304
#define AB_OFF  (W2B_OFF + 128 * WB_STRIDE)       // 51712  a[2][128]
#define TB_OFF  (AB_OFF + 256)                    // 51968  t[2][128]
#define B2_OFF  (TB_OFF + 256)                    // 52224  b2[128]
#define SMEM_FLOATS (B2_OFF + 128)                // 52352
#define SMEM_BYTES  (SMEM_FLOATS * 4)             // 209408 bytes

// round-to-nearest tf32 (unbiased; HW mma would otherwise truncate)
static __device__ __forceinline__ float tf32r(float x) {
    uint32_t u;
    asm("cvt.rna.tf32.f32 %0, %1;" : "=r"(u) : "f"(x));
    return __uint_as_float(u);
}

static __device__ __forceinline__ float4 tf32r4(float4 v) {
    v.x = tf32r(v.x); v.y = tf32r(v.y); v.z = tf32r(v.z); v.w = tf32r(v.w);
    return v;
}

static __device__ __forceinline__ void mma8(float c[4], const uint32_t a[4],
                                            const uint32_t b[2]) {
    asm volatile(
        "mma.sync.aligned.m16n8k8.row.col.f32.tf32.tf32.f32 "
        "{%0,%1,%2,%3}, {%4,%5,%6,%7}, {%8,%9}, {%0,%1,%2,%3};"
        : "+f"(c[0]), "+f"(c[1]), "+f"(c[2]), "+f"(c[3])
        : "r"(a[0]), "r"(a[1]), "r"(a[2]), "r"(a[3]), "r"(b[0]), "r"(b[1]));
}

// 128x128x128 warp-tiled GEMM: acc[2][8][4] += X(128x128 @ xoff, stride 132)
//                                            @ W(128x128 @ woff, stride 136)
static __device__ __forceinline__ void do_gemm(const float* __restrict__ sm,
                                               int xoff, int woff,
                                               float acc[2][8][4],
                                               int warp_m, int warp_n, int lane) {
    const int r0 = warp_m * 32 + (lane >> 2);
    const int nn = warp_n * 64 + (lane >> 2);
    #pragma unroll 4
    for (int k0 = 0; k0 < 128; k0 += 8) {
        const int c0 = k0 + (lane & 3);
        uint32_t afr[2][4];
        #pragma unroll
        for (int mi = 0; mi < 2; mi++) {
            const float* base = sm + xoff + (r0 + mi * 16) * XB_STRIDE;
            afr[mi][0] = __float_as_uint(base[c0]);
            afr[mi][1] = __float_as_uint(base[8 * XB_STRIDE + c0]);
            afr[mi][2] = __float_as_uint(base[c0 + 4]);
            afr[mi][3] = __float_as_uint(base[8 * XB_STRIDE + c0 + 4]);
        }
        uint32_t bfr[8][2];
        const float* wb = sm + woff + (k0 + (lane & 3)) * WB_STRIDE + nn;
        #pragma unroll
        for (int ni = 0; ni < 8; ni++) {
            bfr[ni][0] = __float_as_uint(wb[ni * 8]);
            bfr[ni][1] = __float_as_uint(wb[4 * WB_STRIDE + ni * 8]);
        }
        #pragma unroll
        for (int mi = 0; mi < 2; mi++)
            #pragma unroll
            for (int ni = 0; ni < 8; ni++)
                mma8(acc[mi][ni], afr[mi], bfr[ni]);
    }
}

__global__ void __launch_bounds__(NTHREADS, 1)
tmlp_kernel(const float* __restrict__ embs, const float* __restrict__ W1,
            const float* __restrict__ b1,   const float* __restrict__ W2,
            const float* __restrict__ b2,   float* __restrict__ out) {
    extern __shared__ float sm[];
    const int tid    = threadIdx.x;
    const int lane   = tid & 31;
    const int wid    = tid >> 5;
    const int warp_m = wid >> 1;     // 0..3
    const int warp_n = wid & 1;      // 0..1
    const int cta_b0 = blockIdx.x * BPC;

    // ---- load weights once per CTA (tf32-rounded, float4), b2 (fp32) -------
    for (int idx = tid; idx < 128 * 32; idx += NTHREADS) {
        int k = idx >> 5, c4 = (idx & 31) << 2;
        float4 w1v = *(const float4*)&W1[(128 + k) * DIMV + c4];
        float4 w2v = *(const float4*)&W2[k * DIMV + c4];
        *(float4*)&sm[W1B_OFF + k * WB_STRIDE + c4] = tf32r4(w1v);
        *(float4*)&sm[W2B_OFF + k * WB_STRIDE + c4] = tf32r4(w2v);
    }
    if (tid < 128) sm[B2_OFF + tid] = b2[tid];

    for (int it = 0; it < BPC / 2; it++) {
        const int b0 = cta_b0 + it * 2;

        // ---- load targets t[2][128] (fp32) and x tile (tf32, float4) -------
        {
            int i = tid >> 7, k = tid & 127;
            sm[TB_OFF + tid] = embs[((b0 + i) * NODES) * DIMV + k];
        }
        for (int idx = tid; idx < 128 * 32; idx += NTHREADS) {
            int r = idx >> 5, c4 = (idx & 31) << 2;
            float4 v = make_float4(0.f, 0.f, 0.f, 0.f);
            if (r < 126) {
                int nb   = (r >= 63);
                int node = 1 + (r - nb * 63);
                v = tf32r4(*(const float4*)&embs[((b0 + nb) * NODES + node) * DIMV + c4]);
            }
            *(float4*)&sm[XB_OFF + r * XB_STRIDE + c4] = v;
        }
        __syncthreads();

        // ---- a = t @ W1_top + b1 (full fp32; 2x128 outputs) ----------------
        {
            int i = tid >> 7, j = tid & 127;
            float s = b1[j];
            #pragma unroll 8
            for (int k = 0; k < 128; k++)
                s += sm[TB_OFF + i * 128 + k] * W1[k * DIMV + j];
            sm[AB_OFF + i * 128 + j] = s;
        }

        // ---- GEMM1: x @ W1_bot ---------------------------------------------
        float acc[2][8][4] = {};
        do_gemm(sm, XB_OFF, W1B_OFF, acc, warp_m, warp_n, lane);
        __syncthreads();   // everyone done reading XB (and AB written)

        // ---- epilogue 1: h1 = tf32(relu(acc + a[batch])) -> XB -------------
        #pragma unroll
        for (int mi = 0; mi < 2; mi++) {
            int rb = warp_m * 32 + mi * 16 + (lane >> 2);
            #pragma unroll
            for (int ni = 0; ni < 8; ni++) {
                int cb = warp_n * 64 + ni * 8 + 2 * (lane & 3);
                #pragma unroll
                for (int q = 0; q < 4; q++) {
                    int r  = rb + (q >= 2 ? 8 : 0);
                    int c  = cb + (q & 1);
                    int bi = (r >= 63);
                    float h = acc[mi][ni][q] + sm[AB_OFF + bi * 128 + c];
                    sm[XB_OFF + r * XB_STRIDE + c] = tf32r(fmaxf(h, 0.0f));
                }
            }
        }
        __syncthreads();

        // ---- GEMM2: h1 @ W2 -------------------------------------------------
        float acc2[2][8][4] = {};
        do_gemm(sm, XB_OFF, W2B_OFF, acc2, warp_m, warp_n, lane);
        __syncthreads();   // everyone done reading XB

        // ---- epilogue 2: h2 = relu(acc2 + b2) (fp32) -> XB -----------------
        #pragma unroll
        for (int mi = 0; mi < 2; mi++) {
            int rb = warp_m * 32 + mi * 16 + (lane >> 2);
            #pragma unroll
            for (int ni = 0; ni < 8; ni++) {
                int cb = warp_n * 64 + ni * 8 + 2 * (lane & 3);
                #pragma unroll
                for (int q = 0; q < 4; q++) {
                    int r = rb + (q >= 2 ? 8 : 0);
                    int c = cb + (q & 1);
                    float h = acc2[mi][ni][q] + sm[B2_OFF + c];
                    sm[XB_OFF + r * XB_STRIDE + c] = fmaxf(h, 0.0f);
                }
            }
        }
        __syncthreads();

        // ---- segment reduction: out[b0+i][col] = sum_{r<63} h2[i*63+r][col]
        {
            int i = tid >> 7, col = tid & 127;
            float s = 0.0f;
            #pragma unroll 9
            for (int r = 0; r < 63; r++)
                s += sm[XB_OFF + (i * 63 + r) * XB_STRIDE + col];
            out[(b0 + i) * DIMV + col] = s;
        }
        __syncthreads();   // before next iteration overwrites XB/TB/AB
    }
}

// ============================================================================
// Inputs (metadata order): embs f32 [4096*64,128], batch_idx i64 (unused),
// W1 f32 [256,128], b1 f32 [128], W2 f32 [128,128], b2 f32 [128],
// then scalar params (unused). Output: f32 [4096,128].
// ============================================================================
extern "C" void kernel_launch(void* const* d_in, const int* in_sizes, int n_in,
                              void* d_out, int out_size) {
    (void)in_sizes; (void)n_in; (void)out_size;
    const float* embs = (const float*)d_in[0];
    const float* W1   = (const float*)d_in[2];
    const float* b1   = (const float*)d_in[3];
    const float* W2   = (const float*)d_in[4];
    const float* b2   = (const float*)d_in[5];
    float* out        = (float*)d_out;

    cudaFuncSetAttribute(tmlp_kernel, cudaFuncAttributeMaxDynamicSharedMemorySize,
                         SMEM_BYTES);
    tmlp_kernel<<<NBATCH / BPC, NTHREADS, SMEM_BYTES>>>(embs, W1, b1, W2, b2, out);
}

// round 7
// speedup vs baseline: 1.7154x; 1.7154x over previous
#include <cuda_runtime.h>
#include <cstdint>

// ============================================================================
// TargetMLPReadout on sm_103a — mma.sync tf32 fused kernel (round 6 resubmit;
// rounds 5-6 hit GPU broker timeouts, design has never run)
//   out[b] = sum_{n=1..63} relu(relu([t_b;e_bn]@W1 + b1)@W2 + b2)
//   a_b = t_b@W1_top + b1          (tf32 mini-MMA, once per CTA, 8 batches)
//   h1  = relu(e@W1_bot + a_b)     (tf32 mma.sync, per 128x128 tile)
//   h2  = relu(h1@W2 + b2)
//   out[b] = sum over 63 rows of h2
// R5 vs R4: 512 threads (16 warps), hoisted a-compute as mini-MMA,
//           x-tile register prefetch overlapping GEMM2, float2 epilogue stores.
// ============================================================================

#define DIMV     128
#define NODES    64
#define NBATCH   4096
#define BPC      8
#define NTHREADS 512

#define XB_STRIDE 132
#define WB_STRIDE 136
#define XB_OFF  0
#define W1B_OFF (128 * XB_STRIDE)                 // 16896
#define W2B_OFF (W1B_OFF + 128 * WB_STRIDE)       // 34304
#define AB_OFF  (W2B_OFF + 128 * WB_STRIDE)       // 51712  a[8][132]
#define TB_OFF  (AB_OFF + 8 * XB_STRIDE)          // 52768  t[16][132] (rows 8-15 zero)
#define B2_OFF  (TB_OFF + 16 * XB_STRIDE)         // 54880  b2[128]
#define SMEM_FLOATS (B2_OFF + 128)                // 55008
#define SMEM_BYTES  (SMEM_FLOATS * 4)             // 220032 bytes

static __device__ __forceinline__ float tf32r(float x) {
    uint32_t u;
    asm("cvt.rna.tf32.f32 %0, %1;" : "=r"(u) : "f"(x));
    return __uint_as_float(u);
}
static __device__ __forceinline__ float4 tf32r4(float4 v) {
    v.x = tf32r(v.x); v.y = tf32r(v.y); v.z = tf32r(v.z); v.w = tf32r(v.w);
    return v;
}

static __device__ __forceinline__ void mma8(float c[4], const uint32_t a[4],
                                            const uint32_t b[2]) {
    asm volatile(
        "mma.sync.aligned.m16n8k8.row.col.f32.tf32.tf32.f32 "
        "{%0,%1,%2,%3}, {%4,%5,%6,%7}, {%8,%9}, {%0,%1,%2,%3};"
        : "+f"(c[0]), "+f"(c[1]), "+f"(c[2]), "+f"(c[3])
        : "r"(a[0]), "r"(a[1]), "r"(a[2]), "r"(a[3]), "r"(b[0]), "r"(b[1]));
}

// 128x128x128 warp-tiled GEMM, 16 warps: warp tile 32(M) x 32(N)
static __device__ __forceinline__ void do_gemm(const float* __restrict__ sm,
                                               int xoff, int woff,
                                               float acc[2][4][4],
                                               int warp_m, int warp_n, int lane) {
    const int r0 = warp_m * 32 + (lane >> 2);
    const int nn = warp_n * 32 + (lane >> 2);
    #pragma unroll
    for (int k0 = 0; k0 < 128; k0 += 8) {
        const int c0 = k0 + (lane & 3);
        uint32_t afr[2][4];
        #pragma unroll
        for (int mi = 0; mi < 2; mi++) {
            const float* base = sm + xoff + (r0 + mi * 16) * XB_STRIDE;
            afr[mi][0] = __float_as_uint(base[c0]);
            afr[mi][1] = __float_as_uint(base[8 * XB_STRIDE + c0]);
            afr[mi][2] = __float_as_uint(base[c0 + 4]);
            afr[mi][3] = __float_as_uint(base[8 * XB_STRIDE + c0 + 4]);
        }
        uint32_t bfr[4][2];
        const float* wb = sm + woff + c0 * WB_STRIDE + nn;
        #pragma unroll
        for (int ni = 0; ni < 4; ni++) {
            bfr[ni][0] = __float_as_uint(wb[ni * 8]);
            bfr[ni][1] = __float_as_uint(wb[4 * WB_STRIDE + ni * 8]);
        }
        #pragma unroll
        for (int mi = 0; mi < 2; mi++)
            #pragma unroll
            for (int ni = 0; ni < 4; ni++)
                mma8(acc[mi][ni], afr[mi], bfr[ni]);
    }
}

__global__ void __launch_bounds__(NTHREADS, 1)
tmlp_kernel(const float* __restrict__ embs, const float* __restrict__ W1,
            const float* __restrict__ b1,   const float* __restrict__ W2,
            const float* __restrict__ b2,   float* __restrict__ out) {
    extern __shared__ float sm[];
    const int tid    = threadIdx.x;
    const int lane   = tid & 31;
    const int wid    = tid >> 5;
    const int warp_m = wid >> 2;     // 0..3
    const int warp_n = wid & 3;      // 0..3
    const int cta_b0 = blockIdx.x * BPC;

    // ---- preamble: weights (tf32), W1_top staged in XB, targets, b2 --------
    for (int idx = tid; idx < 128 * 32; idx += NTHREADS) {
        int k = idx >> 5, c4 = (idx & 31) << 2;
        *(float4*)&sm[W1B_OFF + k * WB_STRIDE + c4] =
            tf32r4(*(const float4*)&W1[(128 + k) * DIMV + c4]);
        *(float4*)&sm[W2B_OFF + k * WB_STRIDE + c4] =
            tf32r4(*(const float4*)&W2[k * DIMV + c4]);
        *(float4*)&sm[XB_OFF + k * XB_STRIDE + c4] =            // W1_top (transient)
            tf32r4(*(const float4*)&W1[k * DIMV + c4]);
    }
    for (int idx = tid; idx < 8 * DIMV; idx += NTHREADS) {      // targets, tf32
        int r = idx >> 7, k = idx & 127;
        sm[TB_OFF + r * XB_STRIDE + k] = tf32r(embs[(uint64_t)(cta_b0 + r) * NODES * DIMV + k]);
    }
    for (int idx = tid; idx < 8 * XB_STRIDE; idx += NTHREADS)   // zero rows 8..15
        sm[TB_OFF + 8 * XB_STRIDE + idx] = 0.0f;
    if (tid < 128) sm[B2_OFF + tid] = b2[tid];
    __syncthreads();

    // ---- mini-MMA: a[8][128] = t @ W1_top + b1 (one 8-col slice per warp) --
    {
        float c[4] = {0.f, 0.f, 0.f, 0.f};
        const int n0 = wid * 8;
        #pragma unroll
        for (int k0 = 0; k0 < 128; k0 += 8) {
            const int c0 = k0 + (lane & 3);
            uint32_t a[4], b[2];
            const float* tb = sm + TB_OFF + (lane >> 2) * XB_STRIDE;
            a[0] = __float_as_uint(tb[c0]);
            a[1] = __float_as_uint(tb[8 * XB_STRIDE + c0]);      // zeros
            a[2] = __float_as_uint(tb[c0 + 4]);
            a[3] = __float_as_uint(tb[8 * XB_STRIDE + c0 + 4]);  // zeros
            const float* wt = sm + XB_OFF + c0 * XB_STRIDE + n0 + (lane >> 2);
            b[0] = __float_as_uint(wt[0]);
            b[1] = __float_as_uint(wt[4 * XB_STRIDE]);
            mma8(c, a, b);
        }
        const int r   = lane >> 2;
        const int col = n0 + 2 * (lane & 3);
        sm[AB_OFF + r * XB_STRIDE + col]     = c[0] + b1[col];
        sm[AB_OFF + r * XB_STRIDE + col + 1] = c[1] + b1[col + 1];
    }
    __syncthreads();   // AB done; XB free for x tiles

    // ---- load x tile for iteration 0 ---------------------------------------
    for (int idx = tid; idx < 128 * 32; idx += NTHREADS) {
        int r = idx >> 5, c4 = (idx & 31) << 2;
        float4 v = make_float4(0.f, 0.f, 0.f, 0.f);
        if (r < 126) {
            int nb = (r >= 63), node = 1 + (r - nb * 63);
            v = tf32r4(*(const float4*)&embs[((uint64_t)(cta_b0 + nb) * NODES + node) * DIMV + c4]);
        }
        *(float4*)&sm[XB_OFF + r * XB_STRIDE + c4] = v;
    }
    __syncthreads();

    for (int it = 0; it < BPC / 2; it++) {
        const int b0 = cta_b0 + it * 2;

        // ---- GEMM1: x @ W1_bot ---------------------------------------------
        float acc[2][4][4] = {};
        do_gemm(sm, XB_OFF, W1B_OFF, acc, warp_m, warp_n, lane);
        __syncthreads();

        // ---- epilogue 1: h1 = tf32(relu(acc + a[batch])) -> XB -------------
        #pragma unroll
        for (int mi = 0; mi < 2; mi++) {
            const int rb = warp_m * 32 + mi * 16 + (lane >> 2);
            const int bi0 = it * 2 + (rb >= 63);
            const int bi1 = it * 2 + (rb + 8 >= 63);
            #pragma unroll
            for (int ni = 0; ni < 4; ni++) {
                const int cb = warp_n * 32 + ni * 8 + 2 * (lane & 3);
                float2 v01, v23;
                v01.x = tf32r(fmaxf(acc[mi][ni][0] + sm[AB_OFF + bi0 * XB_STRIDE + cb],     0.f));
                v01.y = tf32r(fmaxf(acc[mi][ni][1] + sm[AB_OFF + bi0 * XB_STRIDE + cb + 1], 0.f));
                v23.x = tf32r(fmaxf(acc[mi][ni][2] + sm[AB_OFF + bi1 * XB_STRIDE + cb],     0.f));
                v23.y = tf32r(fmaxf(acc[mi][ni][3] + sm[AB_OFF + bi1 * XB_STRIDE + cb + 1], 0.f));
                *(float2*)&sm[XB_OFF + rb * XB_STRIDE + cb]       = v01;
                *(float2*)&sm[XB_OFF + (rb + 8) * XB_STRIDE + cb] = v23;
            }
        }
        __syncthreads();

        // ---- prefetch next x tile into registers (overlaps GEMM2) ----------
        const bool haspf = (it < BPC / 2 - 1);
        float4 pf[8];
        if (haspf) {
            const int nb0 = b0 + 2;
            #pragma unroll
            for (int p = 0; p < 8; p++) {
                int idx = tid + p * NTHREADS;
                int r = idx >> 5, c4 = (idx & 31) << 2;
                pf[p] = make_float4(0.f, 0.f, 0.f, 0.f);
                if (r < 126) {
                    int nb = (r >= 63), node = 1 + (r - nb * 63);
                    pf[p] = *(const float4*)&embs[((uint64_t)(nb0 + nb) * NODES + node) * DIMV + c4];
                }
            }
        }

        // ---- GEMM2: h1 @ W2 -------------------------------------------------
        float acc2[2][4][4] = {};
        do_gemm(sm, XB_OFF, W2B_OFF, acc2, warp_m, warp_n, lane);
        __syncthreads();

        // ---- epilogue 2: h2 = relu(acc2 + b2) -> XB ------------------------
        #pragma unroll
        for (int mi = 0; mi < 2; mi++) {
            const int rb = warp_m * 32 + mi * 16 + (lane >> 2);
            #pragma unroll
            for (int ni = 0; ni < 4; ni++) {
                const int cb = warp_n * 32 + ni * 8 + 2 * (lane & 3);
                float2 v01, v23;
                v01.x = fmaxf(acc2[mi][ni][0] + sm[B2_OFF + cb],     0.f);
                v01.y = fmaxf(acc2[mi][ni][1] + sm[B2_OFF + cb + 1], 0.f);
                v23.x = fmaxf(acc2[mi][ni][2] + sm[B2_OFF + cb],     0.f);
                v23.y = fmaxf(acc2[mi][ni][3] + sm[B2_OFF + cb + 1], 0.f);
                *(float2*)&sm[XB_OFF + rb * XB_STRIDE + cb]       = v01;
                *(float2*)&sm[XB_OFF + (rb + 8) * XB_STRIDE + cb] = v23;
            }
        }
        __syncthreads();

        // ---- segment reduction: out[b0+i][col] = sum_{r<63} h2[i*63+r][col]
        if (tid < 256) {
            const int i = tid >> 7, col = tid & 127;
            float s = 0.0f;
            #pragma unroll 9
            for (int r = 0; r < 63; r++)
                s += sm[XB_OFF + (i * 63 + r) * XB_STRIDE + col];
            out[(uint64_t)(b0 + i) * DIMV + col] = s;
        }
        __syncthreads();

        // ---- commit prefetched tile to XB ----------------------------------
        if (haspf) {
            #pragma unroll
            for (int p = 0; p < 8; p++) {
                int idx = tid + p * NTHREADS;
                int r = idx >> 5, c4 = (idx & 31) << 2;
                *(float4*)&sm[XB_OFF + r * XB_STRIDE + c4] = tf32r4(pf[p]);
            }
        }
        __syncthreads();
    }
}

// ============================================================================
// Inputs (metadata order): embs f32 [4096*64,128], batch_idx i64 (unused),
// W1 f32 [256,128], b1 f32 [128], W2 f32 [128,128], b2 f32 [128],
// then scalar params (unused). Output: f32 [4096,128].
// ============================================================================
extern "C" void kernel_launch(void* const* d_in, const int* in_sizes, int n_in,
                              void* d_out, int out_size) {
    (void)in_sizes; (void)n_in; (void)out_size;
    const float* embs = (const float*)d_in[0];
    const float* W1   = (const float*)d_in[2];
    const float* b1   = (const float*)d_in[3];
    const float* W2   = (const float*)d_in[4];
    const float* b2   = (const float*)d_in[5];
    float* out        = (float*)d_out;

    cudaFuncSetAttribute(tmlp_kernel, cudaFuncAttributeMaxDynamicSharedMemorySize,
                         SMEM_BYTES);
    tmlp_kernel<<<NBATCH / BPC, NTHREADS, SMEM_BYTES>>>(embs, W1, b1, W2, b2, out);
}

// round 13
// speedup vs baseline: 1.9178x; 1.1180x over previous
#include <cuda_runtime.h>
#include <cstdint>

// ============================================================================
// TargetMLPReadout on sm_103a — mma.sync tf32, persistent CTAs (round 12
// resubmit; rounds 9-12 hit GPU broker timeouts, design has never run)
//   pre-kernel: g_a[b] = t_b @ W1_top + b1       (full fp32, 2MB scratch)
//   main (148 persistent CTAs, strided tiles of 2 batches):
//     h1 = relu(e@W1_bot + a_b)  (tf32 mma.sync)
//     h2 = relu(h1@W2 + b2)      (tf32 mma.sync)
//     out[b] = sum over 63 rows of h2  (512-thread split reduce)
// tcgen05 is unavailable: harness builds compute_103 PTX (no 'a' feature set).
// ============================================================================

#define DIMV     128
#define NODES    64
#define NBATCH   4096
#define NTILES   2048          // 2 batches per 128-row tile
#define NTHREADS 512
#define GRID     148

// shared memory layout (floats)
#define XB_STRIDE 132
#define WB_STRIDE 136
#define XB_OFF  0
#define W1B_OFF (128 * XB_STRIDE)                 // 16896
#define W2B_OFF (W1B_OFF + 128 * WB_STRIDE)       // 34304
#define AB_OFF  (W2B_OFF + 128 * WB_STRIDE)       // 51712  a[2][128]
#define B2_OFF  (AB_OFF + 256)                    // 51968  b2[128]
#define PS_OFF  (B2_OFF + 128)                    // 52096  reduce partials[512]
#define SMEM_FLOATS (PS_OFF + 512)                // 52608
#define SMEM_BYTES  (SMEM_FLOATS * 4)             // 210432 bytes

__device__ float g_a[NBATCH * DIMV];              // 2MB scratch (allowed)

static __device__ __forceinline__ float tf32r(float x) {
    uint32_t u;
    asm("cvt.rna.tf32.f32 %0, %1;" : "=r"(u) : "f"(x));
    return __uint_as_float(u);
}
static __device__ __forceinline__ float4 tf32r4(float4 v) {
    v.x = tf32r(v.x); v.y = tf32r(v.y); v.z = tf32r(v.z); v.w = tf32r(v.w);
    return v;
}

static __device__ __forceinline__ void mma8(float c[4], const uint32_t a[4],
                                            const uint32_t b[2]) {
    asm volatile(
        "mma.sync.aligned.m16n8k8.row.col.f32.tf32.tf32.f32 "
        "{%0,%1,%2,%3}, {%4,%5,%6,%7}, {%8,%9}, {%0,%1,%2,%3};"
        : "+f"(c[0]), "+f"(c[1]), "+f"(c[2]), "+f"(c[3])
        : "r"(a[0]), "r"(a[1]), "r"(a[2]), "r"(a[3]), "r"(b[0]), "r"(b[1]));
}

// 128x128x128 warp-tiled GEMM, 16 warps: warp tile 32(M) x 32(N)
static __device__ __forceinline__ void do_gemm(const float* __restrict__ sm,
                                               int xoff, int woff,
                                               float acc[2][4][4],
                                               int warp_m, int warp_n, int lane) {
    const int r0 = warp_m * 32 + (lane >> 2);
    const int nn = warp_n * 32 + (lane >> 2);
    #pragma unroll
    for (int k0 = 0; k0 < 128; k0 += 8) {
        const int c0 = k0 + (lane & 3);
        uint32_t afr[2][4];
        #pragma unroll
        for (int mi = 0; mi < 2; mi++) {
            const float* base = sm + xoff + (r0 + mi * 16) * XB_STRIDE;
            afr[mi][0] = __float_as_uint(base[c0]);
            afr[mi][1] = __float_as_uint(base[8 * XB_STRIDE + c0]);
            afr[mi][2] = __float_as_uint(base[c0 + 4]);
            afr[mi][3] = __float_as_uint(base[8 * XB_STRIDE + c0 + 4]);
        }
        uint32_t bfr[4][2];
        const float* wb = sm + woff + c0 * WB_STRIDE + nn;
        #pragma unroll
        for (int ni = 0; ni < 4; ni++) {
            bfr[ni][0] = __float_as_uint(wb[ni * 8]);
            bfr[ni][1] = __float_as_uint(wb[4 * WB_STRIDE + ni * 8]);
        }
        #pragma unroll
        for (int mi = 0; mi < 2; mi++)
            #pragma unroll
            for (int ni = 0; ni < 4; ni++)
                mma8(acc[mi][ni], afr[mi], bfr[ni]);
    }
}

// ---------------------------------------------------------------------------
// Pre-kernel: g_a[b][j] = sum_k t_b[k] * W1[k][j] + b1[j]   (full fp32)
// ---------------------------------------------------------------------------
__global__ void __launch_bounds__(256)
a_kernel(const float* __restrict__ embs, const float* __restrict__ W1,
         const float* __restrict__ b1) {
    const int gid = blockIdx.x * 256 + threadIdx.x;
    const int b = gid >> 7, j = gid & 127;
    const float* t = embs + (uint64_t)b * NODES * DIMV;
    float s = b1[j];
    #pragma unroll 8
    for (int k = 0; k < 128; k++)
        s += t[k] * W1[k * DIMV + j];
    g_a[gid] = s;
}

// ---------------------------------------------------------------------------
__global__ void __launch_bounds__(NTHREADS, 1)
tmlp_kernel(const float* __restrict__ embs, const float* __restrict__ W1,
            const float* __restrict__ b2,   const float* __restrict__ W2,
            float* __restrict__ out) {
    extern __shared__ float sm[];
    const int tid    = threadIdx.x;
    const int lane   = tid & 31;
    const int wid    = tid >> 5;
    const int warp_m = wid >> 2;     // 0..3
    const int warp_n = wid & 3;      // 0..3

    // ---- preamble (once): weights (tf32, float4), b2 ------------------------
    for (int idx = tid; idx < 128 * 32; idx += NTHREADS) {
        int k = idx >> 5, c4 = (idx & 31) << 2;
        *(float4*)&sm[W1B_OFF + k * WB_STRIDE + c4] =
            tf32r4(*(const float4*)&W1[(128 + k) * DIMV + c4]);
        *(float4*)&sm[W2B_OFF + k * WB_STRIDE + c4] =
            tf32r4(*(const float4*)&W2[k * DIMV + c4]);
    }
    if (tid < 128) sm[B2_OFF + tid] = b2[tid];

    // ---- first tile: x (tf32) + a rows --------------------------------------
    int t = blockIdx.x;
    {
        const int b0 = t * 2;
        for (int idx = tid; idx < 128 * 32; idx += NTHREADS) {
            int r = idx >> 5, c4 = (idx & 31) << 2;
            float4 v = make_float4(0.f, 0.f, 0.f, 0.f);
            if (r < 126) {
                int nb = (r >= 63), node = 1 + (r - nb * 63);
                v = tf32r4(*(const float4*)&embs[((uint64_t)(b0 + nb) * NODES + node) * DIMV + c4]);
            }
            *(float4*)&sm[XB_OFF + r * XB_STRIDE + c4] = v;
        }
        if (tid < 256) sm[AB_OFF + tid] = g_a[t * 256 + tid];
    }
    __syncthreads();

    for (; t < NTILES; t += GRID) {
        const int b0 = t * 2;
        const int tn = t + GRID;
        const bool haspf = (tn < NTILES);

        // ---- GEMM1: x @ W1_bot ---------------------------------------------
        float acc[2][4][4] = {};
        do_gemm(sm, XB_OFF, W1B_OFF, acc, warp_m, warp_n, lane);
        __syncthreads();

        // ---- epilogue 1: h1 = tf32(relu(acc + a[batch])) -> XB -------------
        #pragma unroll
        for (int mi = 0; mi < 2; mi++) {
            const int rb = warp_m * 32 + mi * 16 + (lane >> 2);
            const int bi0 = (rb >= 63);
            const int bi1 = (rb + 8 >= 63);
            #pragma unroll
            for (int ni = 0; ni < 4; ni++) {
                const int cb = warp_n * 32 + ni * 8 + 2 * (lane & 3);
                float2 v01, v23;
                v01.x = tf32r(fmaxf(acc[mi][ni][0] + sm[AB_OFF + bi0 * 128 + cb],     0.f));
                v01.y = tf32r(fmaxf(acc[mi][ni][1] + sm[AB_OFF + bi0 * 128 + cb + 1], 0.f));
                v23.x = tf32r(fmaxf(acc[mi][ni][2] + sm[AB_OFF + bi1 * 128 + cb],     0.f));
                v23.y = tf32r(fmaxf(acc[mi][ni][3] + sm[AB_OFF + bi1 * 128 + cb + 1], 0.f));
                *(float2*)&sm[XB_OFF + rb * XB_STRIDE + cb]       = v01;
                *(float2*)&sm[XB_OFF + (rb + 8) * XB_STRIDE + cb] = v23;
            }
        }
        __syncthreads();

        // ---- prefetch next tile (x + a rows) into registers ----------------
        float4 pf[8];
        float  pfa = 0.0f;
        if (haspf) {
            const int nb0 = tn * 2;
            #pragma unroll
            for (int p = 0; p < 8; p++) {
                int idx = tid + p * NTHREADS;
                int r = idx >> 5, c4 = (idx & 31) << 2;
                pf[p] = make_float4(0.f, 0.f, 0.f, 0.f);
                if (r < 126) {
                    int nb = (r >= 63), node = 1 + (r - nb * 63);
                    pf[p] = *(const float4*)&embs[((uint64_t)(nb0 + nb) * NODES + node) * DIMV + c4];
                }
            }
            if (tid < 256) pfa = g_a[tn * 256 + tid];
        }

        // ---- GEMM2: h1 @ W2 -------------------------------------------------
        float acc2[2][4][4] = {};
        do_gemm(sm, XB_OFF, W2B_OFF, acc2, warp_m, warp_n, lane);
        __syncthreads();

        // ---- epilogue 2: h2 = relu(acc2 + b2) -> XB ------------------------
        #pragma unroll
        for (int mi = 0; mi < 2; mi++) {
            const int rb = warp_m * 32 + mi * 16 + (lane >> 2);
            #pragma unroll
            for (int ni = 0; ni < 4; ni++) {
                const int cb = warp_n * 32 + ni * 8 + 2 * (lane & 3);
                float2 v01, v23;
                v01.x = fmaxf(acc2[mi][ni][0] + sm[B2_OFF + cb],     0.f);
                v01.y = fmaxf(acc2[mi][ni][1] + sm[B2_OFF + cb + 1], 0.f);
                v23.x = fmaxf(acc2[mi][ni][2] + sm[B2_OFF + cb],     0.f);
                v23.y = fmaxf(acc2[mi][ni][3] + sm[B2_OFF + cb + 1], 0.f);
                *(float2*)&sm[XB_OFF + rb * XB_STRIDE + cb]       = v01;
                *(float2*)&sm[XB_OFF + (rb + 8) * XB_STRIDE + cb] = v23;
            }
        }
        __syncthreads();

        // ---- split reduce: 512 threads, rows 0..31 / 32..62 ----------------
        {
            const int half = tid >> 8;          // 0: rows 0..31, 1: rows 32..62
            const int sub  = tid & 255;
            const int bsel = sub >> 7, col = sub & 127;
            const int rbase = bsel * 63 + half * 32;
            const int cnt = half ? 31 : 32;
            float s = 0.0f;
            #pragma unroll 8
            for (int rr = 0; rr < cnt; rr++)
                s += sm[XB_OFF + (rbase + rr) * XB_STRIDE + col];
            sm[PS_OFF + tid] = s;
        }
        __syncthreads();

        // ---- final store + commit prefetched tile --------------------------
        if (tid < 256) {
            const int bsel = tid >> 7, col = tid & 127;
            out[(uint64_t)(b0 + bsel) * DIMV + col] =
                sm[PS_OFF + tid] + sm[PS_OFF + 256 + tid];
        }
        if (haspf) {
            #pragma unroll
            for (int p = 0; p < 8; p++) {
                int idx = tid + p * NTHREADS;
                int r = idx >> 5, c4 = (idx & 31) << 2;
                *(float4*)&sm[XB_OFF + r * XB_STRIDE + c4] = tf32r4(pf[p]);
            }
            if (tid < 256) sm[AB_OFF + tid] = pfa;
        }
        __syncthreads();
    }
}

// ============================================================================
// Inputs (metadata order): embs f32 [4096*64,128], batch_idx i64 (unused),
// W1 f32 [256,128], b1 f32 [128], W2 f32 [128,128], b2 f32 [128],
// then scalar params (unused). Output: f32 [4096,128].
// ============================================================================
extern "C" void kernel_launch(void* const* d_in, const int* in_sizes, int n_in,
                              void* d_out, int out_size) {
    (void)in_sizes; (void)n_in; (void)out_size;
    const float* embs = (const float*)d_in[0];
    const float* W1   = (const float*)d_in[2];
    const float* b1   = (const float*)d_in[3];
    const float* W2   = (const float*)d_in[4];
    const float* b2   = (const float*)d_in[5];
    float* out        = (float*)d_out;

    a_kernel<<<NBATCH * DIMV / 256, 256>>>(embs, W1, b1);

    cudaFuncSetAttribute(tmlp_kernel, cudaFuncAttributeMaxDynamicSharedMemorySize,
                         SMEM_BYTES);
    tmlp_kernel<<<GRID, NTHREADS, SMEM_BYTES>>>(embs, W1, b2, W2, out);
}

// round 14
// speedup vs baseline: 2.0461x; 1.0669x over previous
#include <cuda_runtime.h>
#include <cstdint>

// ============================================================================
// TargetMLPReadout on sm_103a — mma.sync tf32, persistent CTAs, dual-group
// pipelined halves (round 14)
//   pre-kernel: g_a[b] = t_b @ W1_top + b1   (fp32, 4 batches/thread)
//   main (148 persistent CTAs, 512 thr = 2 groups x 8 warps; each group owns
//   one 64-row half = one batch; group-scoped named barriers only):
//     h1 = relu(e@W1_bot + a_b);  h2 = relu(h1@W2 + b2);  out = rowsum(h2)
//   Tile rows: r in [0,64) -> batch b0, node (r&63)+1, pad at r=63;
//              r in [64,128) -> batch b0+1, node (r&63)+1, pad at r=127.
// tcgen05 unavailable (harness emits compute_103 PTX).
// ============================================================================

#define DIMV     128
#define NODES    64
#define NBATCH   4096
#define NTILES   2048
#define NTHREADS 512
#define GRID     148

// shared memory layout (floats)
#define XB_STRIDE 132
#define WB_STRIDE 136
#define XB_OFF  0
#define W1B_OFF (128 * XB_STRIDE)                 // 16896
#define W2B_OFF (W1B_OFF + 128 * WB_STRIDE)       // 34304
#define AB_OFF  (W2B_OFF + 128 * WB_STRIDE)       // 51712  a[2][128]
#define B2_OFF  (AB_OFF + 256)                    // 51968  b2[128]
#define PS_OFF  (B2_OFF + 128)                    // 52096  partials[2][256]
#define SMEM_FLOATS (PS_OFF + 512)                // 52608
#define SMEM_BYTES  (SMEM_FLOATS * 4)             // 210432 bytes

__device__ float g_a[NBATCH * DIMV];              // 2MB scratch

static __device__ __forceinline__ float tf32r(float x) {
    uint32_t u;
    asm("cvt.rna.tf32.f32 %0, %1;" : "=r"(u) : "f"(x));
    return __uint_as_float(u);
}
static __device__ __forceinline__ float4 tf32r4(float4 v) {
    v.x = tf32r(v.x); v.y = tf32r(v.y); v.z = tf32r(v.z); v.w = tf32r(v.w);
    return v;
}

static __device__ __forceinline__ void mma8(float c[4], const uint32_t a[4],
                                            const uint32_t b[2]) {
    asm volatile(
        "mma.sync.aligned.m16n8k8.row.col.f32.tf32.tf32.f32 "
        "{%0,%1,%2,%3}, {%4,%5,%6,%7}, {%8,%9}, {%0,%1,%2,%3};"
        : "+f"(c[0]), "+f"(c[1]), "+f"(c[2]), "+f"(c[3])
        : "r"(a[0]), "r"(a[1]), "r"(a[2]), "r"(a[3]), "r"(b[0]), "r"(b[1]));
}

// 64x128x128 group GEMM: 8 warps (2 warp_m x 4 warp_n), warp tile 32x32.
static __device__ __forceinline__ void do_gemm(const float* __restrict__ sm,
                                               int row_base, int woff,
                                               float acc[2][4][4],
                                               int warp_m, int warp_n, int lane) {
    const int r0 = row_base + warp_m * 32 + (lane >> 2);
    const int nn = warp_n * 32 + (lane >> 2);
    #pragma unroll
    for (int k0 = 0; k0 < 128; k0 += 8) {
        const int c0 = k0 + (lane & 3);
        uint32_t afr[2][4];
        #pragma unroll
        for (int mi = 0; mi < 2; mi++) {
            const float* base = sm + XB_OFF + (r0 + mi * 16) * XB_STRIDE;
            afr[mi][0] = __float_as_uint(base[c0]);
            afr[mi][1] = __float_as_uint(base[8 * XB_STRIDE + c0]);
            afr[mi][2] = __float_as_uint(base[c0 + 4]);
            afr[mi][3] = __float_as_uint(base[8 * XB_STRIDE + c0 + 4]);
        }
        uint32_t bfr[4][2];
        const float* wb = sm + woff + c0 * WB_STRIDE + nn;
        #pragma unroll
        for (int ni = 0; ni < 4; ni++) {
            bfr[ni][0] = __float_as_uint(wb[ni * 8]);
            bfr[ni][1] = __float_as_uint(wb[4 * WB_STRIDE + ni * 8]);
        }
        #pragma unroll
        for (int mi = 0; mi < 2; mi++)
            #pragma unroll
            for (int ni = 0; ni < 4; ni++)
                mma8(acc[mi][ni], afr[mi], bfr[ni]);
    }
}

// ---------------------------------------------------------------------------
// Pre-kernel: g_a[b][j] = sum_k t_b[k]*W1[k][j] + b1[j]; 4 batches per thread.
// ---------------------------------------------------------------------------
__global__ void __launch_bounds__(256)
a_kernel(const float* __restrict__ embs, const float* __restrict__ W1,
         const float* __restrict__ b1) {
    const int tid = threadIdx.x;
    const int j   = tid & 127;
    const int b0  = blockIdx.x * 8 + (tid >> 7) * 4;
    const float* t = embs + (uint64_t)b0 * NODES * DIMV;
    const float bj = b1[j];
    float s0 = bj, s1 = bj, s2 = bj, s3 = bj;
    #pragma unroll 8
    for (int k = 0; k < 128; k++) {
        float w = W1[k * DIMV + j];
        s0 += w * t[k];
        s1 += w * t[NODES * DIMV + k];
        s2 += w * t[2 * NODES * DIMV + k];
        s3 += w * t[3 * NODES * DIMV + k];
    }
    g_a[(b0 + 0) * DIMV + j] = s0;
    g_a[(b0 + 1) * DIMV + j] = s1;
    g_a[(b0 + 2) * DIMV + j] = s2;
    g_a[(b0 + 3) * DIMV + j] = s3;
}

// ---------------------------------------------------------------------------
__global__ void __launch_bounds__(NTHREADS, 1)
tmlp_kernel(const float* __restrict__ embs, const float* __restrict__ W1,
            const float* __restrict__ b2,   const float* __restrict__ W2,
            float* __restrict__ out) {
    extern __shared__ float sm[];
    const int tid    = threadIdx.x;
    const int lane   = tid & 31;
    const int wid    = tid >> 5;
    const int g      = wid >> 3;          // group 0/1: rows [g*64, g*64+64)
    const int w8     = wid & 7;
    const int warp_m = w8 >> 2;           // 0..1
    const int warp_n = w8 & 3;            // 0..3
    const int il     = tid & 255;         // group-local thread id
    const int rowb   = g * 64;
    const uint32_t barid = (uint32_t)(g + 1);

#define GBAR() asm volatile("bar.sync %0, %1;" :: "r"(barid), "r"(256) : "memory")

    // ---- preamble (once): weights (tf32), b2, first tile, a rows ------------
    for (int idx = tid; idx < 128 * 32; idx += NTHREADS) {
        int k = idx >> 5, c4 = (idx & 31) << 2;
        *(float4*)&sm[W1B_OFF + k * WB_STRIDE + c4] =
            tf32r4(*(const float4*)&W1[(128 + k) * DIMV + c4]);
        *(float4*)&sm[W2B_OFF + k * WB_STRIDE + c4] =
            tf32r4(*(const float4*)&W2[k * DIMV + c4]);
    }
    if (tid < 128) sm[B2_OFF + tid] = b2[tid];

    int t = blockIdx.x;
    {
        const int b0 = t * 2;
        for (int idx = tid; idx < 128 * 32; idx += NTHREADS) {
            int r = idx >> 5, c4 = (idx & 31) << 2;
            int h = r >> 6, rr = r & 63;
            float4 v = make_float4(0.f, 0.f, 0.f, 0.f);
            if (rr < 63)
                v = tf32r4(*(const float4*)&embs[((uint64_t)(b0 + h) * NODES + rr + 1) * DIMV + c4]);
            *(float4*)&sm[XB_OFF + r * XB_STRIDE + c4] = v;
        }
        if (tid < 256) sm[AB_OFF + tid] = g_a[t * 256 + tid];
    }
    __syncthreads();

    for (; t < NTILES; t += GRID) {
        const int tn = t + GRID;
        const bool haspf = (tn < NTILES);

        // ---- GEMM1 (own half) ----------------------------------------------
        float acc[2][4][4] = {};
        do_gemm(sm, rowb, W1B_OFF, acc, warp_m, warp_n, lane);
        GBAR();

        // ---- epilogue 1: h1 = tf32(relu(acc + a[g])) -> XB own half --------
        {
            const float* ab = sm + AB_OFF + g * 128;
            #pragma unroll
            for (int mi = 0; mi < 2; mi++) {
                const int rb = rowb + warp_m * 32 + mi * 16 + (lane >> 2);
                #pragma unroll
                for (int ni = 0; ni < 4; ni++) {
                    const int cb = warp_n * 32 + ni * 8 + 2 * (lane & 3);
                    float2 v01, v23;
                    v01.x = tf32r(fmaxf(acc[mi][ni][0] + ab[cb],     0.f));
                    v01.y = tf32r(fmaxf(acc[mi][ni][1] + ab[cb + 1], 0.f));
                    v23.x = tf32r(fmaxf(acc[mi][ni][2] + ab[cb],     0.f));
                    v23.y = tf32r(fmaxf(acc[mi][ni][3] + ab[cb + 1], 0.f));
                    *(float2*)&sm[XB_OFF + rb * XB_STRIDE + cb]       = v01;
                    *(float2*)&sm[XB_OFF + (rb + 8) * XB_STRIDE + cb] = v23;
                }
            }
        }
        GBAR();

        // ---- prefetch next half-tile (own half) + a row --------------------
        float4 pf[8];
        float  pfa = 0.0f;
        if (haspf) {
            const int nb = tn * 2 + g;
            #pragma unroll
            for (int p = 0; p < 8; p++) {
                int idx = il + p * 256;          // 64 rows x 32 float4
                int rr = idx >> 5, c4 = (idx & 31) << 2;
                pf[p] = make_float4(0.f, 0.f, 0.f, 0.f);
                if (rr < 63)
                    pf[p] = *(const float4*)&embs[((uint64_t)nb * NODES + rr + 1) * DIMV + c4];
            }
            if (il < 128) pfa = g_a[tn * 256 + g * 128 + il];
        }

        // ---- GEMM2 (own half) ----------------------------------------------
        float acc2[2][4][4] = {};
        do_gemm(sm, rowb, W2B_OFF, acc2, warp_m, warp_n, lane);
        GBAR();

        // ---- epilogue 2: h2 = relu(acc2 + b2) -> XB own half ---------------
        #pragma unroll
        for (int mi = 0; mi < 2; mi++) {
            const int rb = rowb + warp_m * 32 + mi * 16 + (lane >> 2);
            #pragma unroll
            for (int ni = 0; ni < 4; ni++) {
                const int cb = warp_n * 32 + ni * 8 + 2 * (lane & 3);
                float2 v01, v23;
                v01.x = fmaxf(acc2[mi][ni][0] + sm[B2_OFF + cb],     0.f);
                v01.y = fmaxf(acc2[mi][ni][1] + sm[B2_OFF + cb + 1], 0.f);
                v23.x = fmaxf(acc2[mi][ni][2] + sm[B2_OFF + cb],     0.f);
                v23.y = fmaxf(acc2[mi][ni][3] + sm[B2_OFF + cb + 1], 0.f);
                *(float2*)&sm[XB_OFF + rb * XB_STRIDE + cb]       = v01;
                *(float2*)&sm[XB_OFF + (rb + 8) * XB_STRIDE + cb] = v23;
            }
        }
        GBAR();

        // ---- reduce own half: 256 threads, rows 0..31 / 32..62 -------------
        {
            const int rh = il >> 7, col = il & 127;
            const int r0 = rowb + rh * 32;
            const int cnt = rh ? 31 : 32;
            float s = 0.0f;
            #pragma unroll 8
            for (int rr = 0; rr < cnt; rr++)
                s += sm[XB_OFF + (r0 + rr) * XB_STRIDE + col];
            sm[PS_OFF + g * 256 + il] = s;
        }
        GBAR();

        // ---- store own batch + commit prefetched half ----------------------
        if (il < 128)
            out[(uint64_t)(t * 2 + g) * DIMV + il] =
                sm[PS_OFF + g * 256 + il] + sm[PS_OFF + g * 256 + 128 + il];
        if (haspf) {
            #pragma unroll
            for (int p = 0; p < 8; p++) {
                int idx = il + p * 256;
                int rr = idx >> 5, c4 = (idx & 31) << 2;
                *(float4*)&sm[XB_OFF + (rowb + rr) * XB_STRIDE + c4] = tf32r4(pf[p]);
            }
            if (il < 128) sm[AB_OFF + g * 128 + il] = pfa;
        }
        GBAR();
    }
#undef GBAR
}

// ============================================================================
// Inputs (metadata order): embs f32 [4096*64,128], batch_idx i64 (unused),
// W1 f32 [256,128], b1 f32 [128], W2 f32 [128,128], b2 f32 [128],
// then scalar params (unused). Output: f32 [4096,128].
// ============================================================================
extern "C" void kernel_launch(void* const* d_in, const int* in_sizes, int n_in,
                              void* d_out, int out_size) {
    (void)in_sizes; (void)n_in; (void)out_size;
    const float* embs = (const float*)d_in[0];
    const float* W1   = (const float*)d_in[2];
    const float* b1   = (const float*)d_in[3];
    const float* W2   = (const float*)d_in[4];
    const float* b2   = (const float*)d_in[5];
    float* out        = (float*)d_out;

    a_kernel<<<NBATCH / 8, 256>>>(embs, W1, b1);

    cudaFuncSetAttribute(tmlp_kernel, cudaFuncAttributeMaxDynamicSharedMemorySize,
                         SMEM_BYTES);
    tmlp_kernel<<<GRID, NTHREADS, SMEM_BYTES>>>(embs, W1, b2, W2, out);
}

// round 17
// speedup vs baseline: 2.2722x; 1.1105x over previous
#include <cuda_runtime.h>
#include <cstdint>

// ============================================================================
// TargetMLPReadout on sm_103a — mma.sync tf32, persistent CTAs, dual-group,
// fused a-compute + in-register epilogue-2 reduction (round 16 resubmit;
// rounds 15-16 hit broker timeouts, design has never run)
//   Single kernel. 148 persistent CTAs, 512 thr = 2 groups x 8 warps.
//   Preamble per CTA: a[b] = t_b@W1_top + b1 for its 28 batches -> smem AALL.
//   Per tile half (64 rows = 1 batch per group):
//     h1 = relu(e@W1_bot + a)  (tf32 mma.sync, epi via smem)
//     h2 = relu(h1@W2 + b2)    (tf32 mma.sync, epi fully in registers,
//                               shfl-tree column reduction, pad row masked)
// tcgen05 unavailable (harness emits compute_103 PTX).
// ============================================================================

#define DIMV     128
#define NODES    64
#define NBATCH   4096
#define NTILES   2048
#define NTHREADS 512
#define GRID     148
#define MAXIT    14            // ceil(2048/148)

// shared memory layout (floats)
#define XB_STRIDE 132
#define WB_STRIDE 136
#define XB_OFF  0
#define W1B_OFF (128 * XB_STRIDE)                 // 16896
#define W2B_OFF (W1B_OFF + 128 * WB_STRIDE)       // 34304
#define AALL_OFF (W2B_OFF + 128 * WB_STRIDE)      // 51712  a[14][2][128]
#define B2_OFF  (AALL_OFF + MAXIT * 256)          // 55296  b2[128]
#define PS_OFF  (B2_OFF + 128)                    // 55424  partials[2][256]
#define SMEM_FLOATS (PS_OFF + 512)                // 55936
#define SMEM_BYTES  (SMEM_FLOATS * 4)             // 223744 bytes

static __device__ __forceinline__ float tf32r(float x) {
    uint32_t u;
    asm("cvt.rna.tf32.f32 %0, %1;" : "=r"(u) : "f"(x));
    return __uint_as_float(u);
}
static __device__ __forceinline__ float4 tf32r4(float4 v) {
    v.x = tf32r(v.x); v.y = tf32r(v.y); v.z = tf32r(v.z); v.w = tf32r(v.w);
    return v;
}

static __device__ __forceinline__ void mma8(float c[4], const uint32_t a[4],
                                            const uint32_t b[2]) {
    asm volatile(
        "mma.sync.aligned.m16n8k8.row.col.f32.tf32.tf32.f32 "
        "{%0,%1,%2,%3}, {%4,%5,%6,%7}, {%8,%9}, {%0,%1,%2,%3};"
        : "+f"(c[0]), "+f"(c[1]), "+f"(c[2]), "+f"(c[3])
        : "r"(a[0]), "r"(a[1]), "r"(a[2]), "r"(a[3]), "r"(b[0]), "r"(b[1]));
}

// 64x128x128 group GEMM: 8 warps (2 warp_m x 4 warp_n), warp tile 32x32.
static __device__ __forceinline__ void do_gemm(const float* __restrict__ sm,
                                               int row_base, int woff,
                                               float acc[2][4][4],
                                               int warp_m, int warp_n, int lane) {
    const int r0 = row_base + warp_m * 32 + (lane >> 2);
    const int nn = warp_n * 32 + (lane >> 2);
    #pragma unroll
    for (int k0 = 0; k0 < 128; k0 += 8) {
        const int c0 = k0 + (lane & 3);
        uint32_t afr[2][4];
        #pragma unroll
        for (int mi = 0; mi < 2; mi++) {
            const float* base = sm + XB_OFF + (r0 + mi * 16) * XB_STRIDE;
            afr[mi][0] = __float_as_uint(base[c0]);
            afr[mi][1] = __float_as_uint(base[8 * XB_STRIDE + c0]);
            afr[mi][2] = __float_as_uint(base[c0 + 4]);
            afr[mi][3] = __float_as_uint(base[8 * XB_STRIDE + c0 + 4]);
        }
        uint32_t bfr[4][2];
        const float* wb = sm + woff + c0 * WB_STRIDE + nn;
        #pragma unroll
        for (int ni = 0; ni < 4; ni++) {
            bfr[ni][0] = __float_as_uint(wb[ni * 8]);
            bfr[ni][1] = __float_as_uint(wb[4 * WB_STRIDE + ni * 8]);
        }
        #pragma unroll
        for (int mi = 0; mi < 2; mi++)
            #pragma unroll
            for (int ni = 0; ni < 4; ni++)
                mma8(acc[mi][ni], afr[mi], bfr[ni]);
    }
}

// ---------------------------------------------------------------------------
__global__ void __launch_bounds__(NTHREADS, 1)
tmlp_kernel(const float* __restrict__ embs, const float* __restrict__ W1,
            const float* __restrict__ b1,   const float* __restrict__ W2,
            const float* __restrict__ b2,   float* __restrict__ out) {
    extern __shared__ float sm[];
    const int tid    = threadIdx.x;
    const int lane   = tid & 31;
    const int wid    = tid >> 5;
    const int g      = wid >> 3;          // group 0/1: rows [g*64, g*64+64)
    const int w8     = wid & 7;
    const int warp_m = w8 >> 2;           // 0..1
    const int warp_n = w8 & 3;            // 0..3
    const int il     = tid & 255;         // group-local thread id
    const int rowb   = g * 64;
    const uint32_t barid = (uint32_t)(g + 1);
    const int bid    = blockIdx.x;

#define GBAR() asm volatile("bar.sync %0, %1;" :: "r"(barid), "r"(256) : "memory")

    // ---- preamble 1: weights (tf32), b2, stage this CTA's 28 t-vectors -----
    for (int idx = tid; idx < 128 * 32; idx += NTHREADS) {
        int k = idx >> 5, c4 = (idx & 31) << 2;
        *(float4*)&sm[W1B_OFF + k * WB_STRIDE + c4] =
            tf32r4(*(const float4*)&W1[(128 + k) * DIMV + c4]);
        *(float4*)&sm[W2B_OFF + k * WB_STRIDE + c4] =
            tf32r4(*(const float4*)&W2[k * DIMV + c4]);
    }
    if (tid < 128) sm[B2_OFF + tid] = b2[tid];
    for (int idx = tid; idx < 28 * 128; idx += NTHREADS) {      // t-vectors -> XB
        int m = idx >> 7, k = idx & 127;
        int ti = bid + GRID * (m >> 1);
        float v = 0.0f;
        if (ti < NTILES)
            v = embs[(uint64_t)(2 * ti + (m & 1)) * NODES * DIMV + k];
        sm[XB_OFF + idx] = v;
    }
    __syncthreads();

    // ---- preamble 2: a[m][j] = t_m @ W1_top[:,j] + b1[j] (full fp32) -------
    {
        const int j = tid & 127, q = tid >> 7;     // q-group handles 7 batches
        float s[7];
        const float b1j = b1[j];
        #pragma unroll
        for (int mm = 0; mm < 7; mm++) s[mm] = b1j;
        #pragma unroll 4
        for (int k = 0; k < 128; k++) {
            const float w = W1[k * DIMV + j];
            #pragma unroll
            for (int mm = 0; mm < 7; mm++)
                s[mm] += w * sm[XB_OFF + (q * 7 + mm) * 128 + k];
        }
        __syncthreads();   // all XB t-reads done before overwrite below
        #pragma unroll
        for (int mm = 0; mm < 7; mm++) {
            int m = q * 7 + mm;
            sm[AALL_OFF + (m >> 1) * 256 + (m & 1) * 128 + j] = s[mm];
        }
    }
    __syncthreads();

    // ---- hoist per-thread b2 values for the in-register epilogue ----------
    float b2r[4][2];
    #pragma unroll
    for (int ni = 0; ni < 4; ni++) {
        const int cb = warp_n * 32 + ni * 8 + 2 * (lane & 3);
        b2r[ni][0] = sm[B2_OFF + cb];
        b2r[ni][1] = sm[B2_OFF + cb + 1];
    }
    const bool pad = (warp_m == 1) && ((lane >> 2) == 7);  // local row 63

    // ---- first tile load ----------------------------------------------------
    int t = bid;
    for (int idx = tid; idx < 128 * 32; idx += NTHREADS) {
        int r = idx >> 5, c4 = (idx & 31) << 2;
        int h = r >> 6, rr = r & 63;
        float4 v = make_float4(0.f, 0.f, 0.f, 0.f);
        if (rr < 63)
            v = tf32r4(*(const float4*)&embs[((uint64_t)(2 * t + h) * NODES + rr + 1) * DIMV + c4]);
        *(float4*)&sm[XB_OFF + r * XB_STRIDE + c4] = v;
    }
    __syncthreads();

    int it = 0;
    for (; t < NTILES; t += GRID, it++) {
        const int tn = t + GRID;
        const bool haspf = (tn < NTILES);

        // ---- GEMM1 (own half) ----------------------------------------------
        float acc[2][4][4] = {};
        do_gemm(sm, rowb, W1B_OFF, acc, warp_m, warp_n, lane);
        GBAR();

        // ---- epilogue 1: h1 = tf32(relu(acc + a)) -> XB own half -----------
        {
            const float* ab = sm + AALL_OFF + it * 256 + g * 128;
            #pragma unroll
            for (int mi = 0; mi < 2; mi++) {
                const int rb = rowb + warp_m * 32 + mi * 16 + (lane >> 2);
                #pragma unroll
                for (int ni = 0; ni < 4; ni++) {
                    const int cb = warp_n * 32 + ni * 8 + 2 * (lane & 3);
                    float2 v01, v23;
                    v01.x = tf32r(fmaxf(acc[mi][ni][0] + ab[cb],     0.f));
                    v01.y = tf32r(fmaxf(acc[mi][ni][1] + ab[cb + 1], 0.f));
                    v23.x = tf32r(fmaxf(acc[mi][ni][2] + ab[cb],     0.f));
                    v23.y = tf32r(fmaxf(acc[mi][ni][3] + ab[cb + 1], 0.f));
                    *(float2*)&sm[XB_OFF + rb * XB_STRIDE + cb]       = v01;
                    *(float2*)&sm[XB_OFF + (rb + 8) * XB_STRIDE + cb] = v23;
                }
            }
        }
        GBAR();

        // ---- prefetch next half-tile (own half) ----------------------------
        float4 pf[8];
        if (haspf) {
            const int nb = tn * 2 + g;
            #pragma unroll
            for (int p = 0; p < 8; p++) {
                int idx = il + p * 256;
                int rr = idx >> 5, c4 = (idx & 31) << 2;
                pf[p] = make_float4(0.f, 0.f, 0.f, 0.f);
                if (rr < 63)
                    pf[p] = *(const float4*)&embs[((uint64_t)nb * NODES + rr + 1) * DIMV + c4];
            }
        }

        // ---- GEMM2 (own half) ----------------------------------------------
        float acc2[2][4][4] = {};
        do_gemm(sm, rowb, W2B_OFF, acc2, warp_m, warp_n, lane);

        // ---- epilogue 2 + reduce, fully in registers -----------------------
        // row of acc2[mi][ni][q]: warp_m*32 + mi*16 + (lane>>2) + 8*(q>=2)
        // pad row 63 = (warp_m==1, mi==1, lane>>2==7, q in {2,3}) -> excluded
        #pragma unroll
        for (int ni = 0; ni < 4; ni++) {
            float s0 = fmaxf(acc2[0][ni][0] + b2r[ni][0], 0.f)
                     + fmaxf(acc2[0][ni][2] + b2r[ni][0], 0.f)
                     + fmaxf(acc2[1][ni][0] + b2r[ni][0], 0.f);
            float s1 = fmaxf(acc2[0][ni][1] + b2r[ni][1], 0.f)
                     + fmaxf(acc2[0][ni][3] + b2r[ni][1], 0.f)
                     + fmaxf(acc2[1][ni][1] + b2r[ni][1], 0.f);
            if (!pad) {
                s0 += fmaxf(acc2[1][ni][2] + b2r[ni][0], 0.f);
                s1 += fmaxf(acc2[1][ni][3] + b2r[ni][1], 0.f);
            }
            // reduce over the 8 row-groups (lanes differing in bits 4..2)
            #pragma unroll
            for (int off = 16; off >= 4; off >>= 1) {
                s0 += __shfl_xor_sync(0xffffffffu, s0, off);
                s1 += __shfl_xor_sync(0xffffffffu, s1, off);
            }
            if (lane < 4) {
                const int col = warp_n * 32 + ni * 8 + 2 * lane;
                sm[PS_OFF + g * 256 + warp_m * 128 + col]     = s0;
                sm[PS_OFF + g * 256 + warp_m * 128 + col + 1] = s1;
            }
        }
        GBAR();   // XB reads done (GEMM2) + PS visible

        // ---- store own batch + commit prefetched half ----------------------
        if (il < 128)
            out[(uint64_t)(t * 2 + g) * DIMV + il] =
                sm[PS_OFF + g * 256 + il] + sm[PS_OFF + g * 256 + 128 + il];
        if (haspf) {
            #pragma unroll
            for (int p = 0; p < 8; p++) {
                int idx = il + p * 256;
                int rr = idx >> 5, c4 = (idx & 31) << 2;
                *(float4*)&sm[XB_OFF + (rowb + rr) * XB_STRIDE + c4] = tf32r4(pf[p]);
            }
        }
        GBAR();
    }
#undef GBAR
}

// ============================================================================
// Inputs (metadata order): embs f32 [4096*64,128], batch_idx i64 (unused),
// W1 f32 [256,128], b1 f32 [128], W2 f32 [128,128], b2 f32 [128],
// then scalar params (unused). Output: f32 [4096,128].
// ============================================================================
extern "C" void kernel_launch(void* const* d_in, const int* in_sizes, int n_in,
                              void* d_out, int out_size) {
    (void)in_sizes; (void)n_in; (void)out_size;
    const float* embs = (const float*)d_in[0];
    const float* W1   = (const float*)d_in[2];
    const float* b1   = (const float*)d_in[3];
    const float* W2   = (const float*)d_in[4];
    const float* b2   = (const float*)d_in[5];
    float* out        = (float*)d_out;

    cudaFuncSetAttribute(tmlp_kernel, cudaFuncAttributeMaxDynamicSharedMemorySize,
                         SMEM_BYTES);
    tmlp_kernel<<<GRID, NTHREADS, SMEM_BYTES>>>(embs, W1, b1, W2, b2, out);
}